// round 13
// baseline (speedup 1.0000x reference)
#include <cuda_runtime.h>
#include <cstdint>

// Problem constants
static constexpr int BDIM = 2;
static constexpr int NC   = 16384;
static constexpr int NF   = 65536;
static constexpr int CI   = 128;
static constexpr int CO   = 128;
static constexpr int EC   = 65536;
static constexpr int EF   = 262144;
static constexpr int MROW = BDIM * NC;   // 32768 coarse rows
static constexpr int NT32 = MROW / 32;   // 1024 row-tiles (32-row kernels)
static constexpr int NT64 = MROW / 64;   // 512 row-tiles (64-row kernels)

// Scratch (device globals)
__device__ float g_hb [(size_t)BDIM * NF * CO];        // s+b conv accumulator
__device__ float g_ha [(size_t)BDIM * NC * (CO / 2)];  // a-conv accumulator
__device__ int   g_invmap[NF];
__device__ int   g_cntA[NF + 16];                      // [NF] = nComp
__device__ int   g_csrcC[EF];
__device__ int   g_cdstC[EF];
__device__ int   g_cdstF[EF];
__device__ float g_cs[CO];
__device__ float g_cb[CO];
__device__ float g_Rs[(size_t)MROW * 2 * CO];          // [P_s | Q_s]
__device__ float g_Ra[(size_t)MROW * CO];              // [P_a | Q_a]
__device__ float g_Rb[(size_t)MROW * 2 * CO];          // [P_b | Q_b]

// ---------------------------------------------------------------------------
typedef unsigned long long u64;
__device__ __forceinline__ u64 pk2(float x) {
    u64 r; asm("mov.b64 %0,{%1,%1};" : "=l"(r) : "f"(x)); return r;
}
__device__ __forceinline__ void up2(u64 v, float& x, float& y) {
    asm("mov.b64 {%0,%1},%2;" : "=f"(x), "=f"(y) : "l"(v));
}
__device__ __forceinline__ u64 fma2(u64 a, u64 b, u64 c) {
    u64 d; asm("fma.rn.f32x2 %0,%1,%2,%3;" : "=l"(d) : "l"(a), "l"(b), "l"(c)); return d;
}

// ---------------------------------------------------------------------------
// Setup: invmap via binary search over the SORTED idx array, plus zeroing of
// hb / ha / cntA. One kernel, no prefill passes.
__global__ void setup_kernel(const int* __restrict__ idx, int* __restrict__ invmap,
                             float4* __restrict__ hb, float4* __restrict__ ha,
                             int4* __restrict__ cntA) {
    const int gid = blockIdx.x * blockDim.x + threadIdx.x;
    const int stride = gridDim.x * blockDim.x;
    for (int f = gid; f < NF; f += stride) {
        int lo = 0, hi = NC - 1, res = -1;
        while (lo <= hi) {
            int mid = (lo + hi) >> 1;
            int v = __ldg(&idx[mid]);
            if (v == f) { res = mid; break; }
            if (v < f) lo = mid + 1; else hi = mid - 1;
        }
        invmap[f] = res;
    }
    const float4 z = make_float4(0.f, 0.f, 0.f, 0.f);
    const int n_hb = BDIM * NF * CO / 4;
    for (int i = gid; i < n_hb; i += stride) hb[i] = z;
    const int n_ha = BDIM * NC * 64 / 4;
    for (int i = gid; i < n_ha; i += stride) ha[i] = z;
    const int4 zi = make_int4(0, 0, 0, 0);
    const int n_ct = (NF + 16) / 4;
    for (int i = gid; i < n_ct; i += stride) cntA[i] = zi;
}

__global__ void classify_kernel(const int* __restrict__ ei, const int* __restrict__ invmap,
                                int* __restrict__ cntA, int* __restrict__ csrcC,
                                int* __restrict__ cdstC, int* __restrict__ cdstF,
                                int* __restrict__ ncomp) {
    int e = blockIdx.x * blockDim.x + threadIdx.x;
    if (e >= EF) return;
    int s = ei[e], d = ei[EF + e];
    int sc = invmap[s], dc = invmap[d];
    if (sc < 0 && dc < 0) {
        atomicAdd(&cntA[d], 1);
    } else {
        unsigned act = __activemask();
        int lane = threadIdx.x & 31;
        int rank = __popc(act & ((1u << lane) - 1));
        int leader = __ffs(act) - 1;
        int base = 0;
        if (lane == leader) base = atomicAdd(ncomp, __popc(act));
        base = __shfl_sync(act, base, leader);
        csrcC[base + rank] = sc;
        cdstC[base + rank] = dc;
        cdstF[base + rank] = d;
    }
}

// Both constant LN vectors in one launch: threads 0-127 -> s, 128-255 -> b.
__global__ void constvec2_kernel(const float* __restrict__ sb1, const float* __restrict__ sW2,
                                 const float* __restrict__ sb2, const float* __restrict__ sg,
                                 const float* __restrict__ sbt, float* __restrict__ cs,
                                 const float* __restrict__ bb1, const float* __restrict__ bW2,
                                 const float* __restrict__ bb2, const float* __restrict__ bg,
                                 const float* __restrict__ bbt, float* __restrict__ cb) {
    int half = threadIdx.x / CO;     // 0 = s, 1 = b
    int j    = threadIdx.x % CO;
    const float* b1 = half ? bb1 : sb1;
    const float* W2 = half ? bW2 : sW2;
    const float* b2 = half ? bb2 : sb2;
    const float* g  = half ? bg  : sg;
    const float* bt = half ? bbt : sbt;
    float* c        = half ? cb  : cs;

    float acc = b2[j];
    #pragma unroll 4
    for (int k = 0; k < CO; k++) acc += fmaxf(b1[k], 0.f) * W2[k * CO + j];
    __shared__ float rs_[8], rq_[8];
    float s = acc, qv = acc * acc;
    #pragma unroll
    for (int o = 16; o; o >>= 1) {
        s  += __shfl_xor_sync(0xffffffffu, s, o);
        qv += __shfl_xor_sync(0xffffffffu, qv, o);
    }
    int warp = threadIdx.x >> 5, lane = threadIdx.x & 31;
    if (lane == 0) { rs_[warp] = s; rq_[warp] = qv; }
    __syncthreads();
    float S = 0.f, Q = 0.f;
    int w0 = half * 4;
    #pragma unroll
    for (int w = 0; w < 4; w++) { S += rs_[w0 + w]; Q += rq_[w0 + w]; }
    float mu  = S * (1.f / CO);
    float var = Q * (1.f / CO) - mu * mu;
    c[j] = (acc - mu) * rsqrtf(var + 1e-5f) * g[j] + bt[j];
}

// ---------------------------------------------------------------------------
// PERSISTENT half node GEMM: computes ONE of P / Q from raw W1.
//   mode 0: W = W1_top - W1_bot  (P);  mode 1: W = W1_bot  (Q)
// R rows have stride 2*C; output written at column offset colofs.
// 64-row tiles, 4 rows x 8 cols per thread. 82 KB smem -> 2 blocks/SM.
template <int K, int C>
__global__ void __launch_bounds__(256)
nodegemmHalf_kernel(const float* __restrict__ X, const float* __restrict__ W1,
                    float* __restrict__ R, int mode, int colofs) {
    constexpr int PX  = K + 1;
    constexpr int JU  = 4;         // 8 cols per thread (4 u64)
    constexpr int NXU = K / 16;    // 8 float4 X-prefetch regs (64-row tile, 4 thr/row)

    extern __shared__ float sm[];
    float* sW = sm;              // K*C
    float* sX = sW + K * C;      // 64*PX

    const int tid  = threadIdx.x;
    const int row  = tid >> 2, subx = tid & 3;
    const int eh   = tid & 15, jg = tid >> 4, j0 = jg * 8;

    // Stage weights once per block
    for (int i = tid; i < (K * C) / 4; i += 256) {
        float4 bot = reinterpret_cast<const float4*>(W1)[(K * C) / 4 + i];
        float4 w;
        if (mode == 0) {
            float4 top = reinterpret_cast<const float4*>(W1)[i];
            w = make_float4(top.x - bot.x, top.y - bot.y, top.z - bot.z, top.w - bot.w);
        } else {
            w = bot;
        }
        reinterpret_cast<float4*>(sW)[i] = w;
    }

    float4 xr[NXU];
    auto fetchX = [&](int t) {
        if (t < NT64) {
            const float4* p = reinterpret_cast<const float4*>(
                X + (size_t)(t * 64 + row) * K);
            #pragma unroll
            for (int u = 0; u < NXU; u++) xr[u] = p[subx + 4 * u];
        }
    };

    fetchX(blockIdx.x);
    __syncthreads();   // weights visible; sX untouched

    for (int tile = blockIdx.x; tile < NT64; tile += gridDim.x) {
        #pragma unroll
        for (int u = 0; u < NXU; u++) {
            float* d = sX + row * PX + (subx + 4 * u) * 4;
            d[0] = xr[u].x; d[1] = xr[u].y; d[2] = xr[u].z; d[3] = xr[u].w;
        }
        __syncthreads();

        fetchX(tile + gridDim.x);   // hidden under compute

        u64 acc[4][JU];
        #pragma unroll
        for (int r = 0; r < 4; r++)
            #pragma unroll
            for (int t = 0; t < JU; t++) acc[r][t] = 0ull;

        #pragma unroll 2
        for (int k = 0; k < K; ++k) {
            u64 w[JU];
            {
                ulonglong2 w01 = *reinterpret_cast<const ulonglong2*>(&sW[k * C + j0]);
                ulonglong2 w23 = *reinterpret_cast<const ulonglong2*>(&sW[k * C + j0 + 4]);
                w[0] = w01.x; w[1] = w01.y; w[2] = w23.x; w[3] = w23.y;
            }
            #pragma unroll
            for (int r = 0; r < 4; r++) {
                u64 f = pk2(sX[(eh + 16 * r) * PX + k]);
                #pragma unroll
                for (int t = 0; t < JU; t++) acc[r][t] = fma2(f, w[t], acc[r][t]);
            }
        }

        const int m0 = tile * 64;
        #pragma unroll
        for (int r = 0; r < 4; r++) {
            float* rr = R + (size_t)(m0 + eh + 16 * r) * (2 * C) + colofs + j0;
            float v0, v1, v2, v3, v4, v5, v6, v7;
            up2(acc[r][0], v0, v1); up2(acc[r][1], v2, v3);
            up2(acc[r][2], v4, v5); up2(acc[r][3], v6, v7);
            *reinterpret_cast<float4*>(rr)     = make_float4(v0, v1, v2, v3);
            *reinterpret_cast<float4*>(rr + 4) = make_float4(v4, v5, v6, v7);
        }
        __syncthreads();   // sX consumed before next store
    }
}

// ---------------------------------------------------------------------------
// PERSISTENT fused P|Q node GEMM (cat layout) — used for a (CO2=128) and b
// (K=64, CO2=256), both 2 blocks/SM. Transform-on-load from raw W1.
template <int K, int CO2>
__global__ void __launch_bounds__(256)
nodegemmPQ_kernel(const float* __restrict__ X, const float* __restrict__ W1,
                  float* __restrict__ R) {
    constexpr int C   = CO2 / 2;
    constexpr int PX  = K + 1;
    constexpr int JTT = CO2 / 16;
    constexpr int JU  = JTT / 2;
    constexpr int NXU = K / 32;

    extern __shared__ float sm[];
    float* sW = sm;              // K*CO2
    float* sX = sW + K * CO2;    // 32*PX

    const int tid = threadIdx.x;
    const int row = tid >> 3, subx = tid & 7;
    const int eh = tid & 15, jg = tid >> 4, j0 = jg * JTT;

    for (int i = tid; i < (K * C) / 4; i += 256) {
        float4 top = reinterpret_cast<const float4*>(W1)[i];
        float4 bot = reinterpret_cast<const float4*>(W1)[(K * C) / 4 + i];
        int k = (i * 4) / C;
        int j = (i * 4) % C;
        float4 dif = make_float4(top.x - bot.x, top.y - bot.y,
                                 top.z - bot.z, top.w - bot.w);
        *reinterpret_cast<float4*>(&sW[k * CO2 + j])     = dif;
        *reinterpret_cast<float4*>(&sW[k * CO2 + C + j]) = bot;
    }

    float4 xr[NXU];
    auto fetchX = [&](int t) {
        if (t < NT32) {
            const float4* p = reinterpret_cast<const float4*>(
                X + (size_t)(t * 32 + row) * K);
            #pragma unroll
            for (int u = 0; u < NXU; u++) xr[u] = p[subx + 8 * u];
        }
    };

    fetchX(blockIdx.x);
    __syncthreads();

    for (int tile = blockIdx.x; tile < NT32; tile += gridDim.x) {
        #pragma unroll
        for (int u = 0; u < NXU; u++) {
            float* d = sX + row * PX + (subx + 8 * u) * 4;
            d[0] = xr[u].x; d[1] = xr[u].y; d[2] = xr[u].z; d[3] = xr[u].w;
        }
        __syncthreads();

        fetchX(tile + gridDim.x);

        u64 acc[2][JU];
        #pragma unroll
        for (int i = 0; i < 2; i++)
            #pragma unroll
            for (int t = 0; t < JU; t++) acc[i][t] = 0ull;

        #pragma unroll 2
        for (int k = 0; k < K; ++k) {
            u64 w[JU];
            #pragma unroll
            for (int t = 0; t < JU; t += 2) {
                ulonglong2 wv = *reinterpret_cast<const ulonglong2*>(&sW[k * CO2 + j0 + 2 * t]);
                w[t] = wv.x; w[t + 1] = wv.y;
            }
            u64 f0 = pk2(sX[eh * PX + k]);
            u64 f1 = pk2(sX[(eh + 16) * PX + k]);
            #pragma unroll
            for (int t = 0; t < JU; t++) {
                acc[0][t] = fma2(f0, w[t], acc[0][t]);
                acc[1][t] = fma2(f1, w[t], acc[1][t]);
            }
        }

        const int m0 = tile * 32;
        #pragma unroll
        for (int i = 0; i < 2; i++) {
            float* rr = R + (size_t)(m0 + eh + 16 * i) * CO2 + j0;
            #pragma unroll
            for (int t = 0; t < JU; t += 2) {
                float v0, v1, v2, v3;
                up2(acc[i][t], v0, v1);
                up2(acc[i][t + 1], v2, v3);
                *reinterpret_cast<float4*>(rr + 2 * t) = make_float4(v0, v1, v2, v3);
            }
        }
        __syncthreads();
    }
}

// ---------------------------------------------------------------------------
// Edge kernel: h1 = relu(P[dst]+Q[src]+b1); h2 = h1@W2+b2; LN via per-thread
// partials (shfl-combined jg-pairs for COUT=128); atomic float4 scatter.
// 256 threads. P/Q interleaved in R with row stride 2*COUT (Q = P + COUT).
template <int COUT, bool NCOMP>
__global__ void __launch_bounds__(256, 2)
edgeconv_kernel(const float* __restrict__ R,
                const int* __restrict__ srcC, const int* __restrict__ dstC,
                const int* __restrict__ dstF,
                const float* __restrict__ b1, const float* __restrict__ W2,
                const float* __restrict__ b2, const float* __restrict__ gam,
                const float* __restrict__ bet,
                float* __restrict__ out, int E, int NOUT,
                const int* __restrict__ ncomp) {
    constexpr int LD   = 2 * COUT;
    constexpr int NE   = (COUT == 128) ? 32 : 64;
    constexpr int EOFF = NE / 2;
    constexpr int P2   = COUT + 2;
    constexpr int TPE  = 256 / NE;
    constexpr int NJG  = 256 / EOFF;
    constexpr int NJGR = (COUT == 128) ? NJG / 2 : NJG;  // 8 both ways
    constexpr int PST  = NJGR + 1;                        // 9
    constexpr int JTU  = 4;
    constexpr int NU   = 4;

    extern __shared__ float sm[];
    float* sW2 = sm;
    float* sb1 = sW2 + COUT * COUT;
    float* sb2 = sb1 + COUT;
    float* sg  = sb2 + COUT;
    float* sbt = sg + COUT;
    float* sF  = sbt + COUT;
    float* sPart = sF + NE * P2;
    int*  sdst = (int*)(sPart + NE * PST * 2);

    const int tid = threadIdx.x;
    const int ge  = tid / TPE;
    const int sub = tid % TPE;
    const int eh  = tid & (EOFF - 1);
    const int jg  = tid / EOFF;
    const int j0  = jg * 8;

    for (int i = tid; i < (COUT * COUT) / 4; i += 256)
        reinterpret_cast<float4*>(sW2)[i] = reinterpret_cast<const float4*>(W2)[i];
    if (tid < COUT) {
        sb1[tid] = b1[tid]; sb2[tid] = b2[tid];
        sg[tid]  = gam[tid]; sbt[tid] = bet[tid];
    }

    int Eeff = NCOMP ? *ncomp : E;
    const int total  = 2 * Eeff;
    const int ntiles = (total + NE - 1) / NE;

    float4 pfP[NU], pfQ[NU];
    int pdst = -1;

    auto fetch = [&](int tile) {
        pdst = -1;
        #pragma unroll
        for (int u = 0; u < NU; u++) {
            pfP[u] = make_float4(0.f, 0.f, 0.f, 0.f);
            pfQ[u] = make_float4(0.f, 0.f, 0.f, 0.f);
        }
        int gi = tile * NE + ge;
        if (tile < ntiles && gi < total) {
            int bb = (gi >= Eeff) ? 1 : 0;
            int ee = gi - bb * Eeff;
            int sc = srcC[ee];
            int dc = dstC[ee];
            if (NCOMP) pdst = bb * NOUT + dstF[ee];
            else       pdst = bb * NOUT + dc;
            if (dc >= 0) {
                const float4* pr = reinterpret_cast<const float4*>(
                    R + (size_t)(bb * NC + dc) * LD);
                #pragma unroll
                for (int u = 0; u < NU; u++) pfP[u] = pr[sub + TPE * u];
            }
            if (sc >= 0) {
                const float4* qr = reinterpret_cast<const float4*>(
                    R + (size_t)(bb * NC + sc) * LD + COUT);
                #pragma unroll
                for (int u = 0; u < NU; u++) pfQ[u] = qr[sub + TPE * u];
            }
        }
    };

    fetch(blockIdx.x);

    for (int tile = blockIdx.x; tile < ntiles; tile += gridDim.x) {
        __syncthreads();  // S1

        {
            float2* frow = reinterpret_cast<float2*>(sF + ge * P2);
            #pragma unroll
            for (int u = 0; u < NU; u++) {
                int c4 = sub + TPE * u;
                float4 b = reinterpret_cast<const float4*>(sb1)[c4];
                frow[c4 * 2] = make_float2(fmaxf(pfP[u].x + pfQ[u].x + b.x, 0.f),
                                           fmaxf(pfP[u].y + pfQ[u].y + b.y, 0.f));
                frow[c4 * 2 + 1] = make_float2(fmaxf(pfP[u].z + pfQ[u].z + b.z, 0.f),
                                               fmaxf(pfP[u].w + pfQ[u].w + b.w, 0.f));
            }
            if (sub == 0) sdst[ge] = pdst;
        }
        __syncthreads();  // S2

        fetch(tile + gridDim.x);

        u64 a0[JTU], a1[JTU];
        #pragma unroll
        for (int t = 0; t < JTU; t++) {
            u64 bv = *reinterpret_cast<const u64*>(&sb2[j0 + 2 * t]);
            a0[t] = bv; a1[t] = bv;
        }
        #pragma unroll 4
        for (int k = 0; k < COUT; k += 2) {
            u64 wa[JTU], wb[JTU];
            {
                ulonglong2 t0 = *reinterpret_cast<const ulonglong2*>(&sW2[k * COUT + j0]);
                ulonglong2 t1 = *reinterpret_cast<const ulonglong2*>(&sW2[k * COUT + j0 + 4]);
                wa[0] = t0.x; wa[1] = t0.y; wa[2] = t1.x; wa[3] = t1.y;
            }
            {
                ulonglong2 t0 = *reinterpret_cast<const ulonglong2*>(&sW2[(k + 1) * COUT + j0]);
                ulonglong2 t1 = *reinterpret_cast<const ulonglong2*>(&sW2[(k + 1) * COUT + j0 + 4]);
                wb[0] = t0.x; wb[1] = t0.y; wb[2] = t1.x; wb[3] = t1.y;
            }
            float2 f0 = *reinterpret_cast<const float2*>(&sF[eh * P2 + k]);
            float2 f1 = *reinterpret_cast<const float2*>(&sF[(eh + EOFF) * P2 + k]);
            u64 x0 = pk2(f0.x), x1 = pk2(f0.y);
            u64 y0 = pk2(f1.x), y1 = pk2(f1.y);
            #pragma unroll
            for (int t = 0; t < JTU; t++) {
                a0[t] = fma2(x0, wa[t], a0[t]);
                a0[t] = fma2(x1, wb[t], a0[t]);
                a1[t] = fma2(y0, wa[t], a1[t]);
                a1[t] = fma2(y1, wb[t], a1[t]);
            }
        }

        {
            float s0 = 0.f, q0 = 0.f, s1 = 0.f, q1 = 0.f;
            #pragma unroll
            for (int t = 0; t < JTU; t++) {
                float va, vb;
                up2(a0[t], va, vb); s0 += va + vb; q0 += va * va + vb * vb;
                up2(a1[t], va, vb); s1 += va + vb; q1 += va * va + vb * vb;
            }
            float2* pp = reinterpret_cast<float2*>(sPart);
            if constexpr (COUT == 128) {
                s0 += __shfl_xor_sync(0xffffffffu, s0, 16);
                q0 += __shfl_xor_sync(0xffffffffu, q0, 16);
                s1 += __shfl_xor_sync(0xffffffffu, s1, 16);
                q1 += __shfl_xor_sync(0xffffffffu, q1, 16);
                if ((tid & 16) == 0) {
                    int jh = jg >> 1;
                    pp[eh * PST + jh]          = make_float2(s0, q0);
                    pp[(eh + EOFF) * PST + jh] = make_float2(s1, q1);
                }
            } else {
                pp[eh * PST + jg]          = make_float2(s0, q0);
                pp[(eh + EOFF) * PST + jg] = make_float2(s1, q1);
            }
        }
        __syncthreads();  // S3

        #pragma unroll
        for (int i = 0; i < 2; i++) {
            int e = eh + EOFF * i;
            int row = sdst[e];
            const u64* acc = i ? a1 : a0;
            float s = 0.f, q = 0.f;
            const float2* pp = reinterpret_cast<const float2*>(sPart) + e * PST;
            #pragma unroll
            for (int t = 0; t < NJGR; t++) { float2 v = pp[t]; s += v.x; q += v.y; }
            float mu  = s * (1.f / COUT);
            float var = q * (1.f / COUT) - mu * mu;
            float rs  = rsqrtf(var + 1e-5f);
            if (row >= 0) {
                float4 g0 = *reinterpret_cast<const float4*>(sg + j0);
                float4 g1 = *reinterpret_cast<const float4*>(sg + j0 + 4);
                float4 t0 = *reinterpret_cast<const float4*>(sbt + j0);
                float4 t1 = *reinterpret_cast<const float4*>(sbt + j0 + 4);
                float v0, v1, v2, v3, v4, v5, v6, v7;
                up2(acc[0], v0, v1); up2(acc[1], v2, v3);
                up2(acc[2], v4, v5); up2(acc[3], v6, v7);
                float4 r0, r1;
                r0.x = (v0 - mu) * rs * g0.x + t0.x;
                r0.y = (v1 - mu) * rs * g0.y + t0.y;
                r0.z = (v2 - mu) * rs * g0.z + t0.z;
                r0.w = (v3 - mu) * rs * g0.w + t0.w;
                r1.x = (v4 - mu) * rs * g1.x + t1.x;
                r1.y = (v5 - mu) * rs * g1.y + t1.y;
                r1.z = (v6 - mu) * rs * g1.z + t1.z;
                r1.w = (v7 - mu) * rs * g1.w + t1.w;
                float* op = &out[(size_t)row * COUT + j0];
                atomicAdd(reinterpret_cast<float4*>(op), r0);
                atomicAdd(reinterpret_cast<float4*>(op + 4), r1);
            }
        }
    }
}

// ---------------------------------------------------------------------------
// out = leaky_relu(hb + cntA[n]*(cs+cb), 0.01)
__global__ void combine_kernel(float* __restrict__ out, const float* __restrict__ hb,
                               const int* __restrict__ cntA,
                               const float* __restrict__ cs, const float* __restrict__ cb) {
    const int c4n = CO / 4;
    int total = BDIM * NF * c4n;
    int i = blockIdx.x * blockDim.x + threadIdx.x;
    int stride = gridDim.x * blockDim.x;
    for (; i < total; i += stride) {
        int j4 = i % c4n;
        int n  = (i / c4n) % NF;
        float cnt = (float)cntA[n];
        float4 b = reinterpret_cast<const float4*>(hb)[i];
        float4 s = reinterpret_cast<const float4*>(cs)[j4];
        float4 t = reinterpret_cast<const float4*>(cb)[j4];
        float4 r;
        r.x = b.x + cnt * (s.x + t.x); r.x = r.x > 0.f ? r.x : 0.01f * r.x;
        r.y = b.y + cnt * (s.y + t.y); r.y = r.y > 0.f ? r.y : 0.01f * r.y;
        r.z = b.z + cnt * (s.z + t.z); r.z = r.z > 0.f ? r.z : 0.01f * r.z;
        r.w = b.w + cnt * (s.w + t.w); r.w = r.w > 0.f ? r.w : 0.01f * r.w;
        reinterpret_cast<float4*>(out)[i] = r;
    }
}

// ---------------------------------------------------------------------------
static constexpr int edge_smem(int COUT) {
    int NE  = (COUT == 128) ? 32 : 64;
    int PST = 9;
    return (COUT * COUT + 4 * COUT + NE * (COUT + 2) + NE * PST * 2) * 4 + NE * 4;
}
static constexpr int ngpq_smem(int K, int CO2) {
    return (K * CO2 + 32 * (K + 1)) * 4;
}
static constexpr int nghalf_smem(int K, int C) {
    return (K * C + 64 * (K + 1)) * 4;
}

extern "C" void kernel_launch(void* const* d_in, const int* in_sizes, int n_in,
                              void* d_out, int out_size) {
    (void)in_sizes; (void)n_in; (void)out_size;
    const float* x    = (const float*)d_in[0];
    const int*   idx  = (const int*)d_in[1];
    const int*   ei_c = (const int*)d_in[2];
    const int*   ei_f = (const int*)d_in[3];
    const float* sW1 = (const float*)d_in[4];
    const float* sb1 = (const float*)d_in[5];
    const float* sW2 = (const float*)d_in[6];
    const float* sb2 = (const float*)d_in[7];
    const float* sg  = (const float*)d_in[8];
    const float* sbt = (const float*)d_in[9];
    const float* aW1 = (const float*)d_in[10];
    const float* ab1 = (const float*)d_in[11];
    const float* aW2 = (const float*)d_in[12];
    const float* ab2 = (const float*)d_in[13];
    const float* ag  = (const float*)d_in[14];
    const float* abt = (const float*)d_in[15];
    const float* bW1 = (const float*)d_in[16];
    const float* bb1 = (const float*)d_in[17];
    const float* bW2 = (const float*)d_in[18];
    const float* bb2 = (const float*)d_in[19];
    const float* bg  = (const float*)d_in[20];
    const float* bbt = (const float*)d_in[21];
    float* out = (float*)d_out;

    float *hb, *ha, *cs, *cb, *Rs, *Ra, *Rb;
    int *invmap, *cntA, *csrcC, *cdstC, *cdstF;
    cudaGetSymbolAddress((void**)&hb,    g_hb);
    cudaGetSymbolAddress((void**)&ha,    g_ha);
    cudaGetSymbolAddress((void**)&invmap,g_invmap);
    cudaGetSymbolAddress((void**)&cntA,  g_cntA);
    cudaGetSymbolAddress((void**)&csrcC, g_csrcC);
    cudaGetSymbolAddress((void**)&cdstC, g_cdstC);
    cudaGetSymbolAddress((void**)&cdstF, g_cdstF);
    cudaGetSymbolAddress((void**)&cs,    g_cs);
    cudaGetSymbolAddress((void**)&cb,    g_cb);
    cudaGetSymbolAddress((void**)&Rs,    g_Rs);
    cudaGetSymbolAddress((void**)&Ra,    g_Ra);
    cudaGetSymbolAddress((void**)&Rb,    g_Rb);
    int* ncomp = cntA + NF;

    constexpr int ES128 = edge_smem(128);
    constexpr int ES64  = edge_smem(64);
    constexpr int NG_H  = nghalf_smem(128, 128);  // 98.3 KB -> 2 blocks/SM
    constexpr int NG_A  = ngpq_smem(128, 128);    // 82 KB   -> 2 blocks/SM
    constexpr int NG_B  = ngpq_smem(64, 256);     // 73.9 KB -> 2 blocks/SM
    cudaFuncSetAttribute(edgeconv_kernel<128, true>,
                         cudaFuncAttributeMaxDynamicSharedMemorySize, ES128);
    cudaFuncSetAttribute(edgeconv_kernel<64, false>,
                         cudaFuncAttributeMaxDynamicSharedMemorySize, ES64);
    cudaFuncSetAttribute(nodegemmHalf_kernel<128, 128>,
                         cudaFuncAttributeMaxDynamicSharedMemorySize, NG_H);
    cudaFuncSetAttribute(nodegemmPQ_kernel<128, 128>,
                         cudaFuncAttributeMaxDynamicSharedMemorySize, NG_A);
    cudaFuncSetAttribute(nodegemmPQ_kernel<64, 256>,
                         cudaFuncAttributeMaxDynamicSharedMemorySize, NG_B);

    // R7-proven launch order (reorders regressed ~55% in R8/R10; keep it).

    // [0] setup: invmap (bsearch over sorted idx) + zero hb/ha/cntA
    setup_kernel<<<1024, 256>>>(idx, invmap, (float4*)hb, (float4*)ha, (int4*)cntA);
    // [1] classify/compact fine edges
    classify_kernel<<<EF / 256, 256>>>(ei_f, invmap, cntA, csrcC, cdstC, cdstF, ncomp);
    // [2] constant LN vectors
    constvec2_kernel<<<1, 2 * CO>>>(sb1, sW2, sb2, sg, sbt, cs,
                                    bb1, bW2, bb2, bg, bbt, cb);
    // [3a][3b] s node GEMM split into P / Q halves (2 blocks/SM each)
    nodegemmHalf_kernel<128, 128><<<296, 256, NG_H>>>(x, sW1, Rs, 0, 0);
    nodegemmHalf_kernel<128, 128><<<296, 256, NG_H>>>(x, sW1, Rs, 1, CO);
    // [4] persistent node GEMM for a (cat, 2 blocks/SM)
    nodegemmPQ_kernel<128, 128><<<296, 256, NG_A>>>(x, aW1, Ra);
    // [5] a-conv (coarse graph) -> ha
    edgeconv_kernel<64, false><<<296, 256, ES64>>>(
        Ra, ei_c, ei_c + EC, ei_c + EC,
        ab1, aW2, ab2, ag, abt, ha, EC, NC, nullptr);
    // [6] persistent node GEMM for b (cat, 2 blocks/SM)
    nodegemmPQ_kernel<64, 256><<<296, 256, NG_B>>>(ha, bW1, Rb);
    // [7] skip-conv -> hb
    edgeconv_kernel<128, true><<<296, 256, ES128>>>(
        Rs, csrcC, cdstC, cdstF,
        sb1, sW2, sb2, sg, sbt, hb, 0, NF, ncomp);
    // [8] b-conv -> hb (accumulates)
    edgeconv_kernel<128, true><<<296, 256, ES128>>>(
        Rb, csrcC, cdstC, cdstF,
        bb1, bW2, bb2, bg, bbt, hb, 0, NF, ncomp);
    // [9] out = leaky_relu(hb + cntA*(cs+cb))
    combine_kernel<<<512, 256>>>(out, hb, cntA, cs, cb);
}

// round 14
// speedup vs baseline: 1.0114x; 1.0114x over previous
#include <cuda_runtime.h>
#include <cstdint>

// Problem constants
static constexpr int BDIM = 2;
static constexpr int NC   = 16384;
static constexpr int NF   = 65536;
static constexpr int CI   = 128;
static constexpr int CO   = 128;
static constexpr int EC   = 65536;
static constexpr int EF   = 262144;
static constexpr int MROW = BDIM * NC;   // 32768 coarse rows
static constexpr int NT32 = MROW / 32;   // 1024 row-tiles

// Scratch (device globals)
__device__ float g_hb [(size_t)BDIM * NF * CO];        // s+b conv accumulator
__device__ float g_ha [(size_t)BDIM * NC * (CO / 2)];  // a-conv accumulator
__device__ int   g_invmap[NF];
__device__ int   g_cntA[NF + 16];                      // [NF] = nComp
__device__ int   g_csrcC[EF];
__device__ int   g_cdstC[EF];
__device__ int   g_cdstF[EF];
__device__ float g_cs[CO];
__device__ float g_cb[CO];
__device__ float g_Rs[(size_t)MROW * 2 * CO];          // [P_s | Q_s]
__device__ float g_Ra[(size_t)MROW * CO];              // [P_a | Q_a]
__device__ float g_Rb[(size_t)MROW * 2 * CO];          // [P_b | Q_b]

// ---------------------------------------------------------------------------
typedef unsigned long long u64;
__device__ __forceinline__ u64 pk2(float x) {
    u64 r; asm("mov.b64 %0,{%1,%1};" : "=l"(r) : "f"(x)); return r;
}
__device__ __forceinline__ void up2(u64 v, float& x, float& y) {
    asm("mov.b64 {%0,%1},%2;" : "=f"(x), "=f"(y) : "l"(v));
}
__device__ __forceinline__ u64 fma2(u64 a, u64 b, u64 c) {
    u64 d; asm("fma.rn.f32x2 %0,%1,%2,%3;" : "=l"(d) : "l"(a), "l"(b), "l"(c)); return d;
}

// ---------------------------------------------------------------------------
// Setup: invmap via binary search over the SORTED idx array, plus zeroing of
// hb / ha / cntA. One kernel, no prefill passes.
__global__ void setup_kernel(const int* __restrict__ idx, int* __restrict__ invmap,
                             float4* __restrict__ hb, float4* __restrict__ ha,
                             int4* __restrict__ cntA) {
    const int gid = blockIdx.x * blockDim.x + threadIdx.x;
    const int stride = gridDim.x * blockDim.x;
    for (int f = gid; f < NF; f += stride) {
        int lo = 0, hi = NC - 1, res = -1;
        while (lo <= hi) {
            int mid = (lo + hi) >> 1;
            int v = __ldg(&idx[mid]);
            if (v == f) { res = mid; break; }
            if (v < f) lo = mid + 1; else hi = mid - 1;
        }
        invmap[f] = res;
    }
    const float4 z = make_float4(0.f, 0.f, 0.f, 0.f);
    const int n_hb = BDIM * NF * CO / 4;
    for (int i = gid; i < n_hb; i += stride) hb[i] = z;
    const int n_ha = BDIM * NC * 64 / 4;
    for (int i = gid; i < n_ha; i += stride) ha[i] = z;
    const int4 zi = make_int4(0, 0, 0, 0);
    const int n_ct = (NF + 16) / 4;
    for (int i = gid; i < n_ct; i += stride) cntA[i] = zi;
}

__global__ void classify_kernel(const int* __restrict__ ei, const int* __restrict__ invmap,
                                int* __restrict__ cntA, int* __restrict__ csrcC,
                                int* __restrict__ cdstC, int* __restrict__ cdstF,
                                int* __restrict__ ncomp) {
    int e = blockIdx.x * blockDim.x + threadIdx.x;
    if (e >= EF) return;
    int s = ei[e], d = ei[EF + e];
    int sc = invmap[s], dc = invmap[d];
    if (sc < 0 && dc < 0) {
        atomicAdd(&cntA[d], 1);
    } else {
        unsigned act = __activemask();
        int lane = threadIdx.x & 31;
        int rank = __popc(act & ((1u << lane) - 1));
        int leader = __ffs(act) - 1;
        int base = 0;
        if (lane == leader) base = atomicAdd(ncomp, __popc(act));
        base = __shfl_sync(act, base, leader);
        csrcC[base + rank] = sc;
        cdstC[base + rank] = dc;
        cdstF[base + rank] = d;
    }
}

// Both constant LN vectors in one launch: threads 0-127 -> s, 128-255 -> b.
__global__ void constvec2_kernel(const float* __restrict__ sb1, const float* __restrict__ sW2,
                                 const float* __restrict__ sb2, const float* __restrict__ sg,
                                 const float* __restrict__ sbt, float* __restrict__ cs,
                                 const float* __restrict__ bb1, const float* __restrict__ bW2,
                                 const float* __restrict__ bb2, const float* __restrict__ bg,
                                 const float* __restrict__ bbt, float* __restrict__ cb) {
    int half = threadIdx.x / CO;     // 0 = s, 1 = b
    int j    = threadIdx.x % CO;
    const float* b1 = half ? bb1 : sb1;
    const float* W2 = half ? bW2 : sW2;
    const float* b2 = half ? bb2 : sb2;
    const float* g  = half ? bg  : sg;
    const float* bt = half ? bbt : sbt;
    float* c        = half ? cb  : cs;

    float acc = b2[j];
    #pragma unroll 4
    for (int k = 0; k < CO; k++) acc += fmaxf(b1[k], 0.f) * W2[k * CO + j];
    __shared__ float rs_[8], rq_[8];
    float s = acc, qv = acc * acc;
    #pragma unroll
    for (int o = 16; o; o >>= 1) {
        s  += __shfl_xor_sync(0xffffffffu, s, o);
        qv += __shfl_xor_sync(0xffffffffu, qv, o);
    }
    int warp = threadIdx.x >> 5, lane = threadIdx.x & 31;
    if (lane == 0) { rs_[warp] = s; rq_[warp] = qv; }
    __syncthreads();
    float S = 0.f, Q = 0.f;
    int w0 = half * 4;
    #pragma unroll
    for (int w = 0; w < 4; w++) { S += rs_[w0 + w]; Q += rq_[w0 + w]; }
    float mu  = S * (1.f / CO);
    float var = Q * (1.f / CO) - mu * mu;
    c[j] = (acc - mu) * rsqrtf(var + 1e-5f) * g[j] + bt[j];
}

// ---------------------------------------------------------------------------
// PERSISTENT fused P|Q node GEMM (cat layout). Weights (transform-on-load from
// raw W1) staged into smem ONCE per block; loops over 32-row tiles with
// register-prefetched X across the sync. R[M, CO2] = X @ [W1a-W1b | W1b].
template <int K, int CO2>
__global__ void __launch_bounds__(256)
nodegemmPQ_kernel(const float* __restrict__ X, const float* __restrict__ W1,
                  float* __restrict__ R) {
    constexpr int C   = CO2 / 2;
    constexpr int PX  = K + 1;
    constexpr int JTT = CO2 / 16;
    constexpr int JU  = JTT / 2;
    constexpr int NXU = K / 32;

    extern __shared__ float sm[];
    float* sW = sm;              // K*CO2
    float* sX = sW + K * CO2;    // 32*PX

    const int tid = threadIdx.x;
    const int row = tid >> 3, subx = tid & 7;
    const int eh = tid & 15, jg = tid >> 4, j0 = jg * JTT;

    for (int i = tid; i < (K * C) / 4; i += 256) {
        float4 top = reinterpret_cast<const float4*>(W1)[i];
        float4 bot = reinterpret_cast<const float4*>(W1)[(K * C) / 4 + i];
        int k = (i * 4) / C;
        int j = (i * 4) % C;
        float4 dif = make_float4(top.x - bot.x, top.y - bot.y,
                                 top.z - bot.z, top.w - bot.w);
        *reinterpret_cast<float4*>(&sW[k * CO2 + j])     = dif;
        *reinterpret_cast<float4*>(&sW[k * CO2 + C + j]) = bot;
    }

    float4 xr[NXU];
    auto fetchX = [&](int t) {
        if (t < NT32) {
            const float4* p = reinterpret_cast<const float4*>(
                X + (size_t)(t * 32 + row) * K);
            #pragma unroll
            for (int u = 0; u < NXU; u++) xr[u] = p[subx + 8 * u];
        }
    };

    fetchX(blockIdx.x);
    __syncthreads();   // weights visible; sX untouched

    for (int tile = blockIdx.x; tile < NT32; tile += gridDim.x) {
        #pragma unroll
        for (int u = 0; u < NXU; u++) {
            float* d = sX + row * PX + (subx + 8 * u) * 4;
            d[0] = xr[u].x; d[1] = xr[u].y; d[2] = xr[u].z; d[3] = xr[u].w;
        }
        __syncthreads();

        fetchX(tile + gridDim.x);   // hidden under compute

        u64 acc[2][JU];
        #pragma unroll
        for (int i = 0; i < 2; i++)
            #pragma unroll
            for (int t = 0; t < JU; t++) acc[i][t] = 0ull;

        #pragma unroll 2
        for (int k = 0; k < K; ++k) {
            u64 w[JU];
            #pragma unroll
            for (int t = 0; t < JU; t += 2) {
                ulonglong2 wv = *reinterpret_cast<const ulonglong2*>(&sW[k * CO2 + j0 + 2 * t]);
                w[t] = wv.x; w[t + 1] = wv.y;
            }
            u64 f0 = pk2(sX[eh * PX + k]);
            u64 f1 = pk2(sX[(eh + 16) * PX + k]);
            #pragma unroll
            for (int t = 0; t < JU; t++) {
                acc[0][t] = fma2(f0, w[t], acc[0][t]);
                acc[1][t] = fma2(f1, w[t], acc[1][t]);
            }
        }

        const int m0 = tile * 32;
        #pragma unroll
        for (int i = 0; i < 2; i++) {
            float* rr = R + (size_t)(m0 + eh + 16 * i) * CO2 + j0;
            #pragma unroll
            for (int t = 0; t < JU; t += 2) {
                float v0, v1, v2, v3;
                up2(acc[i][t], v0, v1);
                up2(acc[i][t + 1], v2, v3);
                *reinterpret_cast<float4*>(rr + 2 * t) = make_float4(v0, v1, v2, v3);
            }
        }
        __syncthreads();   // sX consumed before next store
    }
}

// ---------------------------------------------------------------------------
// Edge kernel: h1 = relu(P[dst]+Q[src]+b1); h2 = h1@W2+b2; LN via per-thread
// partials (shfl-combined jg-pairs for COUT=128); atomic float4 scatter.
// 256 threads. P/Q interleaved in R with row stride 2*COUT (Q = P + COUT).
// 2 syncs/tile: the loop-top barrier is removed (legal because after S3 all
// warps have finished reading sF, and sdst is double-buffered so the next
// tile's h1-phase index store can't race the previous tile's LN reads).
template <int COUT, bool NCOMP>
__global__ void __launch_bounds__(256, 2)
edgeconv_kernel(const float* __restrict__ R,
                const int* __restrict__ srcC, const int* __restrict__ dstC,
                const int* __restrict__ dstF,
                const float* __restrict__ b1, const float* __restrict__ W2,
                const float* __restrict__ b2, const float* __restrict__ gam,
                const float* __restrict__ bet,
                float* __restrict__ out, int E, int NOUT,
                const int* __restrict__ ncomp) {
    constexpr int LD   = 2 * COUT;
    constexpr int NE   = (COUT == 128) ? 32 : 64;
    constexpr int EOFF = NE / 2;
    constexpr int P2   = COUT + 2;
    constexpr int TPE  = 256 / NE;
    constexpr int NJG  = 256 / EOFF;
    constexpr int NJGR = (COUT == 128) ? NJG / 2 : NJG;  // 8 both ways
    constexpr int PST  = NJGR + 1;                        // 9
    constexpr int JTU  = 4;
    constexpr int NU   = 4;

    extern __shared__ float sm[];
    float* sW2 = sm;
    float* sb1 = sW2 + COUT * COUT;
    float* sb2 = sb1 + COUT;
    float* sg  = sb2 + COUT;
    float* sbt = sg + COUT;
    float* sF  = sbt + COUT;
    float* sPart = sF + NE * P2;
    int*  sdst = (int*)(sPart + NE * PST * 2);   // double-buffered: 2*NE

    const int tid = threadIdx.x;
    const int ge  = tid / TPE;
    const int sub = tid % TPE;
    const int eh  = tid & (EOFF - 1);
    const int jg  = tid / EOFF;
    const int j0  = jg * 8;

    for (int i = tid; i < (COUT * COUT) / 4; i += 256)
        reinterpret_cast<float4*>(sW2)[i] = reinterpret_cast<const float4*>(W2)[i];
    if (tid < COUT) {
        sb1[tid] = b1[tid]; sb2[tid] = b2[tid];
        sg[tid]  = gam[tid]; sbt[tid] = bet[tid];
    }

    int Eeff = NCOMP ? *ncomp : E;
    const int total  = 2 * Eeff;
    const int ntiles = (total + NE - 1) / NE;

    float4 pfP[NU], pfQ[NU];
    int pdst = -1;

    auto fetch = [&](int tile) {
        pdst = -1;
        #pragma unroll
        for (int u = 0; u < NU; u++) {
            pfP[u] = make_float4(0.f, 0.f, 0.f, 0.f);
            pfQ[u] = make_float4(0.f, 0.f, 0.f, 0.f);
        }
        int gi = tile * NE + ge;
        if (tile < ntiles && gi < total) {
            int bb = (gi >= Eeff) ? 1 : 0;
            int ee = gi - bb * Eeff;
            int sc = srcC[ee];
            int dc = dstC[ee];
            if (NCOMP) pdst = bb * NOUT + dstF[ee];
            else       pdst = bb * NOUT + dc;
            if (dc >= 0) {
                const float4* pr = reinterpret_cast<const float4*>(
                    R + (size_t)(bb * NC + dc) * LD);
                #pragma unroll
                for (int u = 0; u < NU; u++) pfP[u] = pr[sub + TPE * u];
            }
            if (sc >= 0) {
                const float4* qr = reinterpret_cast<const float4*>(
                    R + (size_t)(bb * NC + sc) * LD + COUT);
                #pragma unroll
                for (int u = 0; u < NU; u++) pfQ[u] = qr[sub + TPE * u];
            }
        }
    };

    fetch(blockIdx.x);
    __syncthreads();   // weights/params staged (replaces the old loop-top S1)

    int par = 0;       // sdst buffer parity

    for (int tile = blockIdx.x; tile < ntiles; tile += gridDim.x) {
        int* sd = sdst + par * NE;

        // ---- h1 = relu(P + Q + b1) -> sF ----
        {
            float2* frow = reinterpret_cast<float2*>(sF + ge * P2);
            #pragma unroll
            for (int u = 0; u < NU; u++) {
                int c4 = sub + TPE * u;
                float4 b = reinterpret_cast<const float4*>(sb1)[c4];
                frow[c4 * 2] = make_float2(fmaxf(pfP[u].x + pfQ[u].x + b.x, 0.f),
                                           fmaxf(pfP[u].y + pfQ[u].y + b.y, 0.f));
                frow[c4 * 2 + 1] = make_float2(fmaxf(pfP[u].z + pfQ[u].z + b.z, 0.f),
                                               fmaxf(pfP[u].w + pfQ[u].w + b.w, 0.f));
            }
            if (sub == 0) sd[ge] = pdst;
        }
        __syncthreads();  // S2: h1 + sdst visible; prev tile fully drained

        fetch(tile + gridDim.x);   // next-tile gathers hidden under GEMM

        u64 a0[JTU], a1[JTU];
        #pragma unroll
        for (int t = 0; t < JTU; t++) {
            u64 bv = *reinterpret_cast<const u64*>(&sb2[j0 + 2 * t]);
            a0[t] = bv; a1[t] = bv;
        }
        #pragma unroll 4
        for (int k = 0; k < COUT; k += 2) {
            u64 wa[JTU], wb[JTU];
            {
                ulonglong2 t0 = *reinterpret_cast<const ulonglong2*>(&sW2[k * COUT + j0]);
                ulonglong2 t1 = *reinterpret_cast<const ulonglong2*>(&sW2[k * COUT + j0 + 4]);
                wa[0] = t0.x; wa[1] = t0.y; wa[2] = t1.x; wa[3] = t1.y;
            }
            {
                ulonglong2 t0 = *reinterpret_cast<const ulonglong2*>(&sW2[(k + 1) * COUT + j0]);
                ulonglong2 t1 = *reinterpret_cast<const ulonglong2*>(&sW2[(k + 1) * COUT + j0 + 4]);
                wb[0] = t0.x; wb[1] = t0.y; wb[2] = t1.x; wb[3] = t1.y;
            }
            float2 f0 = *reinterpret_cast<const float2*>(&sF[eh * P2 + k]);
            float2 f1 = *reinterpret_cast<const float2*>(&sF[(eh + EOFF) * P2 + k]);
            u64 x0 = pk2(f0.x), x1 = pk2(f0.y);
            u64 y0 = pk2(f1.x), y1 = pk2(f1.y);
            #pragma unroll
            for (int t = 0; t < JTU; t++) {
                a0[t] = fma2(x0, wa[t], a0[t]);
                a0[t] = fma2(x1, wb[t], a0[t]);
                a1[t] = fma2(y0, wa[t], a1[t]);
                a1[t] = fma2(y1, wb[t], a1[t]);
            }
        }

        {
            float s0 = 0.f, q0 = 0.f, s1 = 0.f, q1 = 0.f;
            #pragma unroll
            for (int t = 0; t < JTU; t++) {
                float va, vb;
                up2(a0[t], va, vb); s0 += va + vb; q0 += va * va + vb * vb;
                up2(a1[t], va, vb); s1 += va + vb; q1 += va * va + vb * vb;
            }
            float2* pp = reinterpret_cast<float2*>(sPart);
            if constexpr (COUT == 128) {
                s0 += __shfl_xor_sync(0xffffffffu, s0, 16);
                q0 += __shfl_xor_sync(0xffffffffu, q0, 16);
                s1 += __shfl_xor_sync(0xffffffffu, s1, 16);
                q1 += __shfl_xor_sync(0xffffffffu, q1, 16);
                if ((tid & 16) == 0) {
                    int jh = jg >> 1;
                    pp[eh * PST + jh]          = make_float2(s0, q0);
                    pp[(eh + EOFF) * PST + jh] = make_float2(s1, q1);
                }
            } else {
                pp[eh * PST + jg]          = make_float2(s0, q0);
                pp[(eh + EOFF) * PST + jg] = make_float2(s1, q1);
            }
        }
        __syncthreads();  // S3: partials visible; all warps done reading sF

        #pragma unroll
        for (int i = 0; i < 2; i++) {
            int e = eh + EOFF * i;
            int row = sd[e];
            const u64* acc = i ? a1 : a0;
            float s = 0.f, q = 0.f;
            const float2* pp = reinterpret_cast<const float2*>(sPart) + e * PST;
            #pragma unroll
            for (int t = 0; t < NJGR; t++) { float2 v = pp[t]; s += v.x; q += v.y; }
            float mu  = s * (1.f / COUT);
            float var = q * (1.f / COUT) - mu * mu;
            float rs  = rsqrtf(var + 1e-5f);
            if (row >= 0) {
                float4 g0 = *reinterpret_cast<const float4*>(sg + j0);
                float4 g1 = *reinterpret_cast<const float4*>(sg + j0 + 4);
                float4 t0 = *reinterpret_cast<const float4*>(sbt + j0);
                float4 t1 = *reinterpret_cast<const float4*>(sbt + j0 + 4);
                float v0, v1, v2, v3, v4, v5, v6, v7;
                up2(acc[0], v0, v1); up2(acc[1], v2, v3);
                up2(acc[2], v4, v5); up2(acc[3], v6, v7);
                float4 r0, r1;
                r0.x = (v0 - mu) * rs * g0.x + t0.x;
                r0.y = (v1 - mu) * rs * g0.y + t0.y;
                r0.z = (v2 - mu) * rs * g0.z + t0.z;
                r0.w = (v3 - mu) * rs * g0.w + t0.w;
                r1.x = (v4 - mu) * rs * g1.x + t1.x;
                r1.y = (v5 - mu) * rs * g1.y + t1.y;
                r1.z = (v6 - mu) * rs * g1.z + t1.z;
                r1.w = (v7 - mu) * rs * g1.w + t1.w;
                float* op = &out[(size_t)row * COUT + j0];
                atomicAdd(reinterpret_cast<float4*>(op), r0);
                atomicAdd(reinterpret_cast<float4*>(op + 4), r1);
            }
        }
        par ^= 1;
        // no loop-top barrier: next h1 store writes sF (done being read) and
        // the other sdst buffer; sPart's next write is after the next S2.
    }
}

// ---------------------------------------------------------------------------
// out = leaky_relu(hb + cntA[n]*(cs+cb), 0.01)
__global__ void combine_kernel(float* __restrict__ out, const float* __restrict__ hb,
                               const int* __restrict__ cntA,
                               const float* __restrict__ cs, const float* __restrict__ cb) {
    const int c4n = CO / 4;
    int total = BDIM * NF * c4n;
    int i = blockIdx.x * blockDim.x + threadIdx.x;
    int stride = gridDim.x * blockDim.x;
    for (; i < total; i += stride) {
        int j4 = i % c4n;
        int n  = (i / c4n) % NF;
        float cnt = (float)cntA[n];
        float4 b = reinterpret_cast<const float4*>(hb)[i];
        float4 s = reinterpret_cast<const float4*>(cs)[j4];
        float4 t = reinterpret_cast<const float4*>(cb)[j4];
        float4 r;
        r.x = b.x + cnt * (s.x + t.x); r.x = r.x > 0.f ? r.x : 0.01f * r.x;
        r.y = b.y + cnt * (s.y + t.y); r.y = r.y > 0.f ? r.y : 0.01f * r.y;
        r.z = b.z + cnt * (s.z + t.z); r.z = r.z > 0.f ? r.z : 0.01f * r.z;
        r.w = b.w + cnt * (s.w + t.w); r.w = r.w > 0.f ? r.w : 0.01f * r.w;
        reinterpret_cast<float4*>(out)[i] = r;
    }
}

// ---------------------------------------------------------------------------
static constexpr int edge_smem(int COUT) {
    int NE  = (COUT == 128) ? 32 : 64;
    int PST = 9;
    return (COUT * COUT + 4 * COUT + NE * (COUT + 2) + NE * PST * 2) * 4 + 2 * NE * 4;
}
static constexpr int ngpq_smem(int K, int CO2) {
    return (K * CO2 + 32 * (K + 1)) * 4;
}

extern "C" void kernel_launch(void* const* d_in, const int* in_sizes, int n_in,
                              void* d_out, int out_size) {
    (void)in_sizes; (void)n_in; (void)out_size;
    const float* x    = (const float*)d_in[0];
    const int*   idx  = (const int*)d_in[1];
    const int*   ei_c = (const int*)d_in[2];
    const int*   ei_f = (const int*)d_in[3];
    const float* sW1 = (const float*)d_in[4];
    const float* sb1 = (const float*)d_in[5];
    const float* sW2 = (const float*)d_in[6];
    const float* sb2 = (const float*)d_in[7];
    const float* sg  = (const float*)d_in[8];
    const float* sbt = (const float*)d_in[9];
    const float* aW1 = (const float*)d_in[10];
    const float* ab1 = (const float*)d_in[11];
    const float* aW2 = (const float*)d_in[12];
    const float* ab2 = (const float*)d_in[13];
    const float* ag  = (const float*)d_in[14];
    const float* abt = (const float*)d_in[15];
    const float* bW1 = (const float*)d_in[16];
    const float* bb1 = (const float*)d_in[17];
    const float* bW2 = (const float*)d_in[18];
    const float* bb2 = (const float*)d_in[19];
    const float* bg  = (const float*)d_in[20];
    const float* bbt = (const float*)d_in[21];
    float* out = (float*)d_out;

    float *hb, *ha, *cs, *cb, *Rs, *Ra, *Rb;
    int *invmap, *cntA, *csrcC, *cdstC, *cdstF;
    cudaGetSymbolAddress((void**)&hb,    g_hb);
    cudaGetSymbolAddress((void**)&ha,    g_ha);
    cudaGetSymbolAddress((void**)&invmap,g_invmap);
    cudaGetSymbolAddress((void**)&cntA,  g_cntA);
    cudaGetSymbolAddress((void**)&csrcC, g_csrcC);
    cudaGetSymbolAddress((void**)&cdstC, g_cdstC);
    cudaGetSymbolAddress((void**)&cdstF, g_cdstF);
    cudaGetSymbolAddress((void**)&cs,    g_cs);
    cudaGetSymbolAddress((void**)&cb,    g_cb);
    cudaGetSymbolAddress((void**)&Rs,    g_Rs);
    cudaGetSymbolAddress((void**)&Ra,    g_Ra);
    cudaGetSymbolAddress((void**)&Rb,    g_Rb);
    int* ncomp = cntA + NF;

    constexpr int ES128 = edge_smem(128);
    constexpr int ES64  = edge_smem(64);
    constexpr int NG_S  = ngpq_smem(128, 256);  // 147.6 KB -> 1 block/SM
    constexpr int NG_A  = ngpq_smem(128, 128);  // 82 KB    -> 2 blocks/SM
    constexpr int NG_B  = ngpq_smem(64, 256);   // 73.9 KB  -> 2 blocks/SM
    cudaFuncSetAttribute(edgeconv_kernel<128, true>,
                         cudaFuncAttributeMaxDynamicSharedMemorySize, ES128);
    cudaFuncSetAttribute(edgeconv_kernel<64, false>,
                         cudaFuncAttributeMaxDynamicSharedMemorySize, ES64);
    cudaFuncSetAttribute(nodegemmPQ_kernel<128, 256>,
                         cudaFuncAttributeMaxDynamicSharedMemorySize, NG_S);
    cudaFuncSetAttribute(nodegemmPQ_kernel<128, 128>,
                         cudaFuncAttributeMaxDynamicSharedMemorySize, NG_A);
    cudaFuncSetAttribute(nodegemmPQ_kernel<64, 256>,
                         cudaFuncAttributeMaxDynamicSharedMemorySize, NG_B);

    // R7-proven launch order (reorders regressed ~55% in R8/R10; keep it).

    // [0] setup: invmap (bsearch over sorted idx) + zero hb/ha/cntA
    setup_kernel<<<1024, 256>>>(idx, invmap, (float4*)hb, (float4*)ha, (int4*)cntA);
    // [1] classify/compact fine edges
    classify_kernel<<<EF / 256, 256>>>(ei_f, invmap, cntA, csrcC, cdstC, cdstF, ncomp);
    // [2] constant LN vectors
    constvec2_kernel<<<1, 2 * CO>>>(sb1, sW2, sb2, sg, sbt, cs,
                                    bb1, bW2, bb2, bg, bbt, cb);
    // [3] persistent node GEMM for s (cat, 1 block/SM — R13 split regressed)
    nodegemmPQ_kernel<128, 256><<<148, 256, NG_S>>>(x, sW1, Rs);
    // [4] persistent node GEMM for a (cat, 2 blocks/SM)
    nodegemmPQ_kernel<128, 128><<<296, 256, NG_A>>>(x, aW1, Ra);
    // [5] a-conv (coarse graph) -> ha
    edgeconv_kernel<64, false><<<296, 256, ES64>>>(
        Ra, ei_c, ei_c + EC, ei_c + EC,
        ab1, aW2, ab2, ag, abt, ha, EC, NC, nullptr);
    // [6] persistent node GEMM for b (cat, 2 blocks/SM)
    nodegemmPQ_kernel<64, 256><<<296, 256, NG_B>>>(ha, bW1, Rb);
    // [7] skip-conv -> hb
    edgeconv_kernel<128, true><<<296, 256, ES128>>>(
        Rs, csrcC, cdstC, cdstF,
        sb1, sW2, sb2, sg, sbt, hb, 0, NF, ncomp);
    // [8] b-conv -> hb (accumulates)
    edgeconv_kernel<128, true><<<296, 256, ES128>>>(
        Rb, csrcC, cdstC, cdstF,
        bb1, bW2, bb2, bg, bbt, hb, 0, NF, ncomp);
    // [9] out = leaky_relu(hb + cntA*(cs+cb))
    combine_kernel<<<512, 256>>>(out, hb, cntA, cs, cb);
}

// round 15
// speedup vs baseline: 1.0289x; 1.0172x over previous
#include <cuda_runtime.h>
#include <cstdint>

// Problem constants
static constexpr int BDIM = 2;
static constexpr int NC   = 16384;
static constexpr int NF   = 65536;
static constexpr int CI   = 128;
static constexpr int CO   = 128;
static constexpr int EC   = 65536;
static constexpr int EF   = 262144;
static constexpr int MROW = BDIM * NC;   // 32768 coarse rows
static constexpr int NT32 = MROW / 32;   // 1024 row-tiles

// Scratch (device globals)
__device__ float g_hb [(size_t)BDIM * NF * CO];        // s+b conv accumulator
__device__ float g_ha [(size_t)BDIM * NC * (CO / 2)];  // a-conv accumulator
__device__ int   g_invmap[NF];
__device__ int   g_cntA[NF + 16];                      // [NF] = nComp
__device__ int4  g_epack[EF];                          // {srcC, dstC, dstF, 0}
__device__ float g_cs[CO];
__device__ float g_cb[CO];
__device__ float g_Rs[(size_t)MROW * 2 * CO];          // [P_s | Q_s]
__device__ float g_Ra[(size_t)MROW * CO];              // [P_a | Q_a]
__device__ float g_Rb[(size_t)MROW * 2 * CO];          // [P_b | Q_b]

// ---------------------------------------------------------------------------
typedef unsigned long long u64;
__device__ __forceinline__ u64 pk2(float x) {
    u64 r; asm("mov.b64 %0,{%1,%1};" : "=l"(r) : "f"(x)); return r;
}
__device__ __forceinline__ void up2(u64 v, float& x, float& y) {
    asm("mov.b64 {%0,%1},%2;" : "=f"(x), "=f"(y) : "l"(v));
}
__device__ __forceinline__ u64 fma2(u64 a, u64 b, u64 c) {
    u64 d; asm("fma.rn.f32x2 %0,%1,%2,%3;" : "=l"(d) : "l"(a), "l"(b), "l"(c)); return d;
}

// ---------------------------------------------------------------------------
// Setup: invmap via binary search over the SORTED idx array, plus zeroing of
// hb / ha / cntA. One kernel, no prefill passes.
__global__ void setup_kernel(const int* __restrict__ idx, int* __restrict__ invmap,
                             float4* __restrict__ hb, float4* __restrict__ ha,
                             int4* __restrict__ cntA) {
    const int gid = blockIdx.x * blockDim.x + threadIdx.x;
    const int stride = gridDim.x * blockDim.x;
    for (int f = gid; f < NF; f += stride) {
        int lo = 0, hi = NC - 1, res = -1;
        while (lo <= hi) {
            int mid = (lo + hi) >> 1;
            int v = __ldg(&idx[mid]);
            if (v == f) { res = mid; break; }
            if (v < f) lo = mid + 1; else hi = mid - 1;
        }
        invmap[f] = res;
    }
    const float4 z = make_float4(0.f, 0.f, 0.f, 0.f);
    const int n_hb = BDIM * NF * CO / 4;
    for (int i = gid; i < n_hb; i += stride) hb[i] = z;
    const int n_ha = BDIM * NC * 64 / 4;
    for (int i = gid; i < n_ha; i += stride) ha[i] = z;
    const int4 zi = make_int4(0, 0, 0, 0);
    const int n_ct = (NF + 16) / 4;
    for (int i = gid; i < n_ct; i += stride) cntA[i] = zi;
}

// Classify fine edges: both-zero -> per-dst count; else compact PACKED record.
__global__ void classify_kernel(const int* __restrict__ ei, const int* __restrict__ invmap,
                                int* __restrict__ cntA, int4* __restrict__ epack,
                                int* __restrict__ ncomp) {
    int e = blockIdx.x * blockDim.x + threadIdx.x;
    if (e >= EF) return;
    int s = ei[e], d = ei[EF + e];
    int sc = invmap[s], dc = invmap[d];
    if (sc < 0 && dc < 0) {
        atomicAdd(&cntA[d], 1);
    } else {
        unsigned act = __activemask();
        int lane = threadIdx.x & 31;
        int rank = __popc(act & ((1u << lane) - 1));
        int leader = __ffs(act) - 1;
        int base = 0;
        if (lane == leader) base = atomicAdd(ncomp, __popc(act));
        base = __shfl_sync(act, base, leader);
        epack[base + rank] = make_int4(sc, dc, d, 0);
    }
}

// Both constant LN vectors in one launch: threads 0-127 -> s, 128-255 -> b.
__global__ void constvec2_kernel(const float* __restrict__ sb1, const float* __restrict__ sW2,
                                 const float* __restrict__ sb2, const float* __restrict__ sg,
                                 const float* __restrict__ sbt, float* __restrict__ cs,
                                 const float* __restrict__ bb1, const float* __restrict__ bW2,
                                 const float* __restrict__ bb2, const float* __restrict__ bg,
                                 const float* __restrict__ bbt, float* __restrict__ cb) {
    int half = threadIdx.x / CO;     // 0 = s, 1 = b
    int j    = threadIdx.x % CO;
    const float* b1 = half ? bb1 : sb1;
    const float* W2 = half ? bW2 : sW2;
    const float* b2 = half ? bb2 : sb2;
    const float* g  = half ? bg  : sg;
    const float* bt = half ? bbt : sbt;
    float* c        = half ? cb  : cs;

    float acc = b2[j];
    #pragma unroll 4
    for (int k = 0; k < CO; k++) acc += fmaxf(b1[k], 0.f) * W2[k * CO + j];
    __shared__ float rs_[8], rq_[8];
    float s = acc, qv = acc * acc;
    #pragma unroll
    for (int o = 16; o; o >>= 1) {
        s  += __shfl_xor_sync(0xffffffffu, s, o);
        qv += __shfl_xor_sync(0xffffffffu, qv, o);
    }
    int warp = threadIdx.x >> 5, lane = threadIdx.x & 31;
    if (lane == 0) { rs_[warp] = s; rq_[warp] = qv; }
    __syncthreads();
    float S = 0.f, Q = 0.f;
    int w0 = half * 4;
    #pragma unroll
    for (int w = 0; w < 4; w++) { S += rs_[w0 + w]; Q += rq_[w0 + w]; }
    float mu  = S * (1.f / CO);
    float var = Q * (1.f / CO) - mu * mu;
    c[j] = (acc - mu) * rsqrtf(var + 1e-5f) * g[j] + bt[j];
}

// ---------------------------------------------------------------------------
// PERSISTENT fused P|Q node GEMM (cat layout). Weights (transform-on-load from
// raw W1) staged into smem ONCE per block; loops over 32-row tiles with
// register-prefetched X across the sync. R[M, CO2] = X @ [W1a-W1b | W1b].
template <int K, int CO2>
__global__ void __launch_bounds__(256)
nodegemmPQ_kernel(const float* __restrict__ X, const float* __restrict__ W1,
                  float* __restrict__ R) {
    constexpr int C   = CO2 / 2;
    constexpr int PX  = K + 1;
    constexpr int JTT = CO2 / 16;
    constexpr int JU  = JTT / 2;
    constexpr int NXU = K / 32;

    extern __shared__ float sm[];
    float* sW = sm;              // K*CO2
    float* sX = sW + K * CO2;    // 32*PX

    const int tid = threadIdx.x;
    const int row = tid >> 3, subx = tid & 7;
    const int eh = tid & 15, jg = tid >> 4, j0 = jg * JTT;

    for (int i = tid; i < (K * C) / 4; i += 256) {
        float4 top = reinterpret_cast<const float4*>(W1)[i];
        float4 bot = reinterpret_cast<const float4*>(W1)[(K * C) / 4 + i];
        int k = (i * 4) / C;
        int j = (i * 4) % C;
        float4 dif = make_float4(top.x - bot.x, top.y - bot.y,
                                 top.z - bot.z, top.w - bot.w);
        *reinterpret_cast<float4*>(&sW[k * CO2 + j])     = dif;
        *reinterpret_cast<float4*>(&sW[k * CO2 + C + j]) = bot;
    }

    float4 xr[NXU];
    auto fetchX = [&](int t) {
        if (t < NT32) {
            const float4* p = reinterpret_cast<const float4*>(
                X + (size_t)(t * 32 + row) * K);
            #pragma unroll
            for (int u = 0; u < NXU; u++) xr[u] = p[subx + 8 * u];
        }
    };

    fetchX(blockIdx.x);
    __syncthreads();   // weights visible; sX untouched

    for (int tile = blockIdx.x; tile < NT32; tile += gridDim.x) {
        #pragma unroll
        for (int u = 0; u < NXU; u++) {
            float* d = sX + row * PX + (subx + 8 * u) * 4;
            d[0] = xr[u].x; d[1] = xr[u].y; d[2] = xr[u].z; d[3] = xr[u].w;
        }
        __syncthreads();

        fetchX(tile + gridDim.x);   // hidden under compute

        u64 acc[2][JU];
        #pragma unroll
        for (int i = 0; i < 2; i++)
            #pragma unroll
            for (int t = 0; t < JU; t++) acc[i][t] = 0ull;

        #pragma unroll 2
        for (int k = 0; k < K; ++k) {
            u64 w[JU];
            #pragma unroll
            for (int t = 0; t < JU; t += 2) {
                ulonglong2 wv = *reinterpret_cast<const ulonglong2*>(&sW[k * CO2 + j0 + 2 * t]);
                w[t] = wv.x; w[t + 1] = wv.y;
            }
            u64 f0 = pk2(sX[eh * PX + k]);
            u64 f1 = pk2(sX[(eh + 16) * PX + k]);
            #pragma unroll
            for (int t = 0; t < JU; t++) {
                acc[0][t] = fma2(f0, w[t], acc[0][t]);
                acc[1][t] = fma2(f1, w[t], acc[1][t]);
            }
        }

        const int m0 = tile * 32;
        #pragma unroll
        for (int i = 0; i < 2; i++) {
            float* rr = R + (size_t)(m0 + eh + 16 * i) * CO2 + j0;
            #pragma unroll
            for (int t = 0; t < JU; t += 2) {
                float v0, v1, v2, v3;
                up2(acc[i][t], v0, v1);
                up2(acc[i][t + 1], v2, v3);
                *reinterpret_cast<float4*>(rr + 2 * t) = make_float4(v0, v1, v2, v3);
            }
        }
        __syncthreads();   // sX consumed before next store
    }
}

// ---------------------------------------------------------------------------
// Edge kernel: h1 = relu(P[dst]+Q[src]+b1); h2 = h1@W2+b2; LN via per-thread
// partials (shfl-combined jg-pairs for COUT=128); atomic float4 scatter.
// 256 threads, 2 syncs/tile, double-buffered sdst (R14-proven).
// NCOMP path reads packed int4 edge records (one LDG.128 per edge).
template <int COUT, bool NCOMP>
__global__ void __launch_bounds__(256, 2)
edgeconv_kernel(const float* __restrict__ R,
                const int4* __restrict__ epack,
                const int* __restrict__ srcC, const int* __restrict__ dstC,
                const float* __restrict__ b1, const float* __restrict__ W2,
                const float* __restrict__ b2, const float* __restrict__ gam,
                const float* __restrict__ bet,
                float* __restrict__ out, int E, int NOUT,
                const int* __restrict__ ncomp) {
    constexpr int LD   = 2 * COUT;
    constexpr int NE   = (COUT == 128) ? 32 : 64;
    constexpr int EOFF = NE / 2;
    constexpr int P2   = COUT + 2;
    constexpr int TPE  = 256 / NE;
    constexpr int NJG  = 256 / EOFF;
    constexpr int NJGR = (COUT == 128) ? NJG / 2 : NJG;  // 8 both ways
    constexpr int PST  = NJGR + 1;                        // 9
    constexpr int JTU  = 4;
    constexpr int NU   = 4;

    extern __shared__ float sm[];
    float* sW2 = sm;
    float* sb1 = sW2 + COUT * COUT;
    float* sb2 = sb1 + COUT;
    float* sg  = sb2 + COUT;
    float* sbt = sg + COUT;
    float* sF  = sbt + COUT;
    float* sPart = sF + NE * P2;
    int*  sdst = (int*)(sPart + NE * PST * 2);   // double-buffered: 2*NE

    const int tid = threadIdx.x;
    const int ge  = tid / TPE;
    const int sub = tid % TPE;
    const int eh  = tid & (EOFF - 1);
    const int jg  = tid / EOFF;
    const int j0  = jg * 8;

    for (int i = tid; i < (COUT * COUT) / 4; i += 256)
        reinterpret_cast<float4*>(sW2)[i] = reinterpret_cast<const float4*>(W2)[i];
    if (tid < COUT) {
        sb1[tid] = b1[tid]; sb2[tid] = b2[tid];
        sg[tid]  = gam[tid]; sbt[tid] = bet[tid];
    }

    int Eeff = NCOMP ? *ncomp : E;
    const int total  = 2 * Eeff;
    const int ntiles = (total + NE - 1) / NE;

    float4 pfP[NU], pfQ[NU];
    int pdst = -1;

    auto fetch = [&](int tile) {
        pdst = -1;
        #pragma unroll
        for (int u = 0; u < NU; u++) {
            pfP[u] = make_float4(0.f, 0.f, 0.f, 0.f);
            pfQ[u] = make_float4(0.f, 0.f, 0.f, 0.f);
        }
        int gi = tile * NE + ge;
        if (tile < ntiles && gi < total) {
            int bb = (gi >= Eeff) ? 1 : 0;
            int ee = gi - bb * Eeff;
            int sc, dc;
            if (NCOMP) {
                int4 rec = __ldg(&epack[ee]);
                sc = rec.x; dc = rec.y;
                pdst = bb * NOUT + rec.z;
            } else {
                sc = srcC[ee];
                dc = dstC[ee];
                pdst = bb * NOUT + dc;
            }
            if (dc >= 0) {
                const float4* pr = reinterpret_cast<const float4*>(
                    R + (size_t)(bb * NC + dc) * LD);
                #pragma unroll
                for (int u = 0; u < NU; u++) pfP[u] = pr[sub + TPE * u];
            }
            if (sc >= 0) {
                const float4* qr = reinterpret_cast<const float4*>(
                    R + (size_t)(bb * NC + sc) * LD + COUT);
                #pragma unroll
                for (int u = 0; u < NU; u++) pfQ[u] = qr[sub + TPE * u];
            }
        }
    };

    fetch(blockIdx.x);
    __syncthreads();   // weights/params staged

    int par = 0;       // sdst buffer parity

    for (int tile = blockIdx.x; tile < ntiles; tile += gridDim.x) {
        int* sd = sdst + par * NE;

        // ---- h1 = relu(P + Q + b1) -> sF ----
        {
            float2* frow = reinterpret_cast<float2*>(sF + ge * P2);
            #pragma unroll
            for (int u = 0; u < NU; u++) {
                int c4 = sub + TPE * u;
                float4 b = reinterpret_cast<const float4*>(sb1)[c4];
                frow[c4 * 2] = make_float2(fmaxf(pfP[u].x + pfQ[u].x + b.x, 0.f),
                                           fmaxf(pfP[u].y + pfQ[u].y + b.y, 0.f));
                frow[c4 * 2 + 1] = make_float2(fmaxf(pfP[u].z + pfQ[u].z + b.z, 0.f),
                                               fmaxf(pfP[u].w + pfQ[u].w + b.w, 0.f));
            }
            if (sub == 0) sd[ge] = pdst;
        }
        __syncthreads();  // S2: h1 + sdst visible; prev tile fully drained

        fetch(tile + gridDim.x);   // next-tile gathers hidden under GEMM

        u64 a0[JTU], a1[JTU];
        #pragma unroll
        for (int t = 0; t < JTU; t++) {
            u64 bv = *reinterpret_cast<const u64*>(&sb2[j0 + 2 * t]);
            a0[t] = bv; a1[t] = bv;
        }
        #pragma unroll 4
        for (int k = 0; k < COUT; k += 2) {
            u64 wa[JTU], wb[JTU];
            {
                ulonglong2 t0 = *reinterpret_cast<const ulonglong2*>(&sW2[k * COUT + j0]);
                ulonglong2 t1 = *reinterpret_cast<const ulonglong2*>(&sW2[k * COUT + j0 + 4]);
                wa[0] = t0.x; wa[1] = t0.y; wa[2] = t1.x; wa[3] = t1.y;
            }
            {
                ulonglong2 t0 = *reinterpret_cast<const ulonglong2*>(&sW2[(k + 1) * COUT + j0]);
                ulonglong2 t1 = *reinterpret_cast<const ulonglong2*>(&sW2[(k + 1) * COUT + j0 + 4]);
                wb[0] = t0.x; wb[1] = t0.y; wb[2] = t1.x; wb[3] = t1.y;
            }
            float2 f0 = *reinterpret_cast<const float2*>(&sF[eh * P2 + k]);
            float2 f1 = *reinterpret_cast<const float2*>(&sF[(eh + EOFF) * P2 + k]);
            u64 x0 = pk2(f0.x), x1 = pk2(f0.y);
            u64 y0 = pk2(f1.x), y1 = pk2(f1.y);
            #pragma unroll
            for (int t = 0; t < JTU; t++) {
                a0[t] = fma2(x0, wa[t], a0[t]);
                a0[t] = fma2(x1, wb[t], a0[t]);
                a1[t] = fma2(y0, wa[t], a1[t]);
                a1[t] = fma2(y1, wb[t], a1[t]);
            }
        }

        {
            float s0 = 0.f, q0 = 0.f, s1 = 0.f, q1 = 0.f;
            #pragma unroll
            for (int t = 0; t < JTU; t++) {
                float va, vb;
                up2(a0[t], va, vb); s0 += va + vb; q0 += va * va + vb * vb;
                up2(a1[t], va, vb); s1 += va + vb; q1 += va * va + vb * vb;
            }
            float2* pp = reinterpret_cast<float2*>(sPart);
            if constexpr (COUT == 128) {
                s0 += __shfl_xor_sync(0xffffffffu, s0, 16);
                q0 += __shfl_xor_sync(0xffffffffu, q0, 16);
                s1 += __shfl_xor_sync(0xffffffffu, s1, 16);
                q1 += __shfl_xor_sync(0xffffffffu, q1, 16);
                if ((tid & 16) == 0) {
                    int jh = jg >> 1;
                    pp[eh * PST + jh]          = make_float2(s0, q0);
                    pp[(eh + EOFF) * PST + jh] = make_float2(s1, q1);
                }
            } else {
                pp[eh * PST + jg]          = make_float2(s0, q0);
                pp[(eh + EOFF) * PST + jg] = make_float2(s1, q1);
            }
        }
        __syncthreads();  // S3: partials visible; all warps done reading sF

        #pragma unroll
        for (int i = 0; i < 2; i++) {
            int e = eh + EOFF * i;
            int row = sd[e];
            const u64* acc = i ? a1 : a0;
            float s = 0.f, q = 0.f;
            const float2* pp = reinterpret_cast<const float2*>(sPart) + e * PST;
            #pragma unroll
            for (int t = 0; t < NJGR; t++) { float2 v = pp[t]; s += v.x; q += v.y; }
            float mu  = s * (1.f / COUT);
            float var = q * (1.f / COUT) - mu * mu;
            float rs  = rsqrtf(var + 1e-5f);
            if (row >= 0) {
                float4 g0 = *reinterpret_cast<const float4*>(sg + j0);
                float4 g1 = *reinterpret_cast<const float4*>(sg + j0 + 4);
                float4 t0 = *reinterpret_cast<const float4*>(sbt + j0);
                float4 t1 = *reinterpret_cast<const float4*>(sbt + j0 + 4);
                float v0, v1, v2, v3, v4, v5, v6, v7;
                up2(acc[0], v0, v1); up2(acc[1], v2, v3);
                up2(acc[2], v4, v5); up2(acc[3], v6, v7);
                float4 r0, r1;
                r0.x = (v0 - mu) * rs * g0.x + t0.x;
                r0.y = (v1 - mu) * rs * g0.y + t0.y;
                r0.z = (v2 - mu) * rs * g0.z + t0.z;
                r0.w = (v3 - mu) * rs * g0.w + t0.w;
                r1.x = (v4 - mu) * rs * g1.x + t1.x;
                r1.y = (v5 - mu) * rs * g1.y + t1.y;
                r1.z = (v6 - mu) * rs * g1.z + t1.z;
                r1.w = (v7 - mu) * rs * g1.w + t1.w;
                float* op = &out[(size_t)row * COUT + j0];
                atomicAdd(reinterpret_cast<float4*>(op), r0);
                atomicAdd(reinterpret_cast<float4*>(op + 4), r1);
            }
        }
        par ^= 1;
    }
}

// ---------------------------------------------------------------------------
// out = leaky_relu(hb + cntA[n]*(cs+cb), 0.01)
__global__ void combine_kernel(float* __restrict__ out, const float* __restrict__ hb,
                               const int* __restrict__ cntA,
                               const float* __restrict__ cs, const float* __restrict__ cb) {
    const int c4n = CO / 4;
    int total = BDIM * NF * c4n;
    int i = blockIdx.x * blockDim.x + threadIdx.x;
    int stride = gridDim.x * blockDim.x;
    for (; i < total; i += stride) {
        int j4 = i % c4n;
        int n  = (i / c4n) % NF;
        float cnt = (float)cntA[n];
        float4 b = reinterpret_cast<const float4*>(hb)[i];
        float4 s = reinterpret_cast<const float4*>(cs)[j4];
        float4 t = reinterpret_cast<const float4*>(cb)[j4];
        float4 r;
        r.x = b.x + cnt * (s.x + t.x); r.x = r.x > 0.f ? r.x : 0.01f * r.x;
        r.y = b.y + cnt * (s.y + t.y); r.y = r.y > 0.f ? r.y : 0.01f * r.y;
        r.z = b.z + cnt * (s.z + t.z); r.z = r.z > 0.f ? r.z : 0.01f * r.z;
        r.w = b.w + cnt * (s.w + t.w); r.w = r.w > 0.f ? r.w : 0.01f * r.w;
        reinterpret_cast<float4*>(out)[i] = r;
    }
}

// ---------------------------------------------------------------------------
static constexpr int edge_smem(int COUT) {
    int NE  = (COUT == 128) ? 32 : 64;
    int PST = 9;
    return (COUT * COUT + 4 * COUT + NE * (COUT + 2) + NE * PST * 2) * 4 + 2 * NE * 4;
}
static constexpr int ngpq_smem(int K, int CO2) {
    return (K * CO2 + 32 * (K + 1)) * 4;
}

extern "C" void kernel_launch(void* const* d_in, const int* in_sizes, int n_in,
                              void* d_out, int out_size) {
    (void)in_sizes; (void)n_in; (void)out_size;
    const float* x    = (const float*)d_in[0];
    const int*   idx  = (const int*)d_in[1];
    const int*   ei_c = (const int*)d_in[2];
    const int*   ei_f = (const int*)d_in[3];
    const float* sW1 = (const float*)d_in[4];
    const float* sb1 = (const float*)d_in[5];
    const float* sW2 = (const float*)d_in[6];
    const float* sb2 = (const float*)d_in[7];
    const float* sg  = (const float*)d_in[8];
    const float* sbt = (const float*)d_in[9];
    const float* aW1 = (const float*)d_in[10];
    const float* ab1 = (const float*)d_in[11];
    const float* aW2 = (const float*)d_in[12];
    const float* ab2 = (const float*)d_in[13];
    const float* ag  = (const float*)d_in[14];
    const float* abt = (const float*)d_in[15];
    const float* bW1 = (const float*)d_in[16];
    const float* bb1 = (const float*)d_in[17];
    const float* bW2 = (const float*)d_in[18];
    const float* bb2 = (const float*)d_in[19];
    const float* bg  = (const float*)d_in[20];
    const float* bbt = (const float*)d_in[21];
    float* out = (float*)d_out;

    float *hb, *ha, *cs, *cb, *Rs, *Ra, *Rb;
    int *invmap, *cntA;
    int4* epack;
    cudaGetSymbolAddress((void**)&hb,    g_hb);
    cudaGetSymbolAddress((void**)&ha,    g_ha);
    cudaGetSymbolAddress((void**)&invmap,g_invmap);
    cudaGetSymbolAddress((void**)&cntA,  g_cntA);
    cudaGetSymbolAddress((void**)&epack, g_epack);
    cudaGetSymbolAddress((void**)&cs,    g_cs);
    cudaGetSymbolAddress((void**)&cb,    g_cb);
    cudaGetSymbolAddress((void**)&Rs,    g_Rs);
    cudaGetSymbolAddress((void**)&Ra,    g_Ra);
    cudaGetSymbolAddress((void**)&Rb,    g_Rb);
    int* ncomp = cntA + NF;

    constexpr int ES128 = edge_smem(128);
    constexpr int ES64  = edge_smem(64);
    constexpr int NG_S  = ngpq_smem(128, 256);  // 147.6 KB -> 1 block/SM
    constexpr int NG_A  = ngpq_smem(128, 128);  // 82 KB    -> 2 blocks/SM
    constexpr int NG_B  = ngpq_smem(64, 256);   // 73.9 KB  -> 2 blocks/SM
    cudaFuncSetAttribute(edgeconv_kernel<128, true>,
                         cudaFuncAttributeMaxDynamicSharedMemorySize, ES128);
    cudaFuncSetAttribute(edgeconv_kernel<64, false>,
                         cudaFuncAttributeMaxDynamicSharedMemorySize, ES64);
    cudaFuncSetAttribute(nodegemmPQ_kernel<128, 256>,
                         cudaFuncAttributeMaxDynamicSharedMemorySize, NG_S);
    cudaFuncSetAttribute(nodegemmPQ_kernel<128, 128>,
                         cudaFuncAttributeMaxDynamicSharedMemorySize, NG_A);
    cudaFuncSetAttribute(nodegemmPQ_kernel<64, 256>,
                         cudaFuncAttributeMaxDynamicSharedMemorySize, NG_B);

    // R7-proven launch order (reorders regressed ~55% in R8/R10; keep it).

    // [0] setup: invmap (bsearch over sorted idx) + zero hb/ha/cntA
    setup_kernel<<<1024, 256>>>(idx, invmap, (float4*)hb, (float4*)ha, (int4*)cntA);
    // [1] classify/compact fine edges (packed records)
    classify_kernel<<<EF / 256, 256>>>(ei_f, invmap, cntA, epack, ncomp);
    // [2] constant LN vectors
    constvec2_kernel<<<1, 2 * CO>>>(sb1, sW2, sb2, sg, sbt, cs,
                                    bb1, bW2, bb2, bg, bbt, cb);
    // [3] persistent node GEMM for s (cat, 1 block/SM)
    nodegemmPQ_kernel<128, 256><<<148, 256, NG_S>>>(x, sW1, Rs);
    // [4] persistent node GEMM for a (cat, 2 blocks/SM)
    nodegemmPQ_kernel<128, 128><<<296, 256, NG_A>>>(x, aW1, Ra);
    // [5] a-conv (coarse graph) -> ha
    edgeconv_kernel<64, false><<<296, 256, ES64>>>(
        Ra, nullptr, ei_c, ei_c + EC,
        ab1, aW2, ab2, ag, abt, ha, EC, NC, nullptr);
    // [6] persistent node GEMM for b (cat, 2 blocks/SM)
    nodegemmPQ_kernel<64, 256><<<296, 256, NG_B>>>(ha, bW1, Rb);
    // [7] skip-conv -> hb
    edgeconv_kernel<128, true><<<296, 256, ES128>>>(
        Rs, epack, nullptr, nullptr,
        sb1, sW2, sb2, sg, sbt, hb, 0, NF, ncomp);
    // [8] b-conv -> hb (accumulates)
    edgeconv_kernel<128, true><<<296, 256, ES128>>>(
        Rb, epack, nullptr, nullptr,
        bb1, bW2, bb2, bg, bbt, hb, 0, NF, ncomp);
    // [9] out = leaky_relu(hb + cntA*(cs+cb))
    combine_kernel<<<1024, 256>>>(out, hb, cntA, cs, cb);
}